// round 8
// baseline (speedup 1.0000x reference)
#include <cuda_runtime.h>
#include <cstdint>

#define NVEH 16384
#define NT   256
#define H    20

#define VPC   32                 // vehicles per CTA
#define TPC   160                // 4 grps x 40 threads (20 units x 2 parities)
#define NCTA  (NVEH / VPC)       // 512
#define PPT   4                  // vehicle-pairs per thread (8 vehicles)
#define NPAIR 16                 // pairs per CTA
#define RSTRIDE 24               // ull per h row (20 used + 4 pad, bank stagger)

typedef unsigned long long ull;

// Repacked weights:
// gW3[(u*2+par)*50 + slot] = dup'd float2, prescaled.
//   slot 0..22  : gate0 rows (q, leadpos, leadspd, U0..U19)
//   slot 23     : gate0 bias, slot 24: gate0 D-row weight
//   slot 25..47 : gate1 rows, 48: gate1 bias, 49: gate1 D-row weight
// gate0 = i (par0, x0.5) / g (par1, x1); gate1 = f (x0.5) / o (x0.5)
__device__ float2 gW3[40 * 50];
__device__ float4 gWdD4[10];     // (0.7*Wd[2k] dup, 0.7*Wd[2k+1] dup)
__device__ float2 gC1;           // dup(0.7*bd - 0.4)

// ---------- packed f32x2 helpers ----------
__device__ __forceinline__ void ffma2(ull& d, ull a, ull b) {
    asm("fma.rn.f32x2 %0, %1, %2, %0;" : "+l"(d) : "l"(a), "l"(b));
}
__device__ __forceinline__ ull mul2(ull a, ull b) {
    ull r; asm("mul.rn.f32x2 %0, %1, %2;" : "=l"(r) : "l"(a), "l"(b)); return r;
}
__device__ __forceinline__ ull add2(ull a, ull b) {
    ull r; asm("add.rn.f32x2 %0, %1, %2;" : "=l"(r) : "l"(a), "l"(b)); return r;
}
__device__ __forceinline__ ull pack2(float lo, float hi) {
    ull r; asm("mov.b64 %0, {%1, %2};" : "=l"(r) : "f"(lo), "f"(hi)); return r;
}
__device__ __forceinline__ float lo32(ull v) {
    float f; asm("{ .reg .b32 hi; mov.b64 {%0, hi}, %1; }" : "=f"(f) : "l"(v)); return f;
}
__device__ __forceinline__ float hi32(ull v) {
    float f; asm("{ .reg .b32 lo; mov.b64 {lo, %0}, %1; }" : "=f"(f) : "l"(v)); return f;
}
__device__ __forceinline__ float fast_tanh(float x) {
    float y; asm("tanh.approx.f32 %0, %1;" : "=f"(y) : "f"(x)); return y;
}

// ---------- repack ----------
__global__ void repack_kernel(const float* __restrict__ W,
                              const float* __restrict__ U,
                              const float* __restrict__ b,
                              const float* __restrict__ Wd,
                              const float* __restrict__ bd)
{
    int i = blockIdx.x * blockDim.x + threadIdx.x;
    if (i < 40 * 50) {
        int u2 = i / 50, slot = i % 50;
        int u = u2 >> 1, par = u2 & 1;
        int g = slot / 25, loc = slot % 25;
        int col = (g == 0) ? (par ? 40 + u : u) : (par ? 60 + u : 20 + u);
        float s = (g == 0 && par) ? 1.0f : 0.5f;   // tanh-gate full scale, sigmoid x0.5
        float w;
        if (loc == 0)       w = W[80 + col] * 0.025f - W[col] * 0.01f;  // q row
        else if (loc == 1)  w = W[col] * 0.01f;                         // leadpos row
        else if (loc == 2)  w = W[160 + col] * 0.025f;                  // leadspd row
        else if (loc < 23)  w = U[(loc - 3) * 80 + col];                // U rows
        else if (loc == 23) w = b[col];                                 // bias
        else                w = W[80 + col] * 0.025f;                   // D row
        w *= s;
        gW3[i] = make_float2(w, w);
    }
    if (i < 10) {
        float a = 0.7f * Wd[2 * i], c = 0.7f * Wd[2 * i + 1];
        gWdD4[i] = make_float4(a, a, c, c);
    }
    if (i == 10) { float v = 0.7f * bd[0] - 0.4f; gC1 = make_float2(v, v); }
}

__global__ __launch_bounds__(TPC, 2)
void rnncf_kernel(const float* __restrict__ lead_inputs,  // (NVEH, NT, 2)
                  const float* __restrict__ init_state,   // (NVEH, 2)
                  const float* __restrict__ h0,           // (NVEH, H)
                  const float* __restrict__ c0,           // (NVEH, H)
                  float* __restrict__ out,
                  int out_size)
{
    __shared__ ull hbuf[2][NPAIR * RSTRIDE];   // h pairs, double buffered

    const int tid = threadIdx.x;
    const int grp = tid / 40;
    const int r   = tid % 40;
    const int u   = r >> 1;
    const int par = r & 1;

    // ---- weights into registers ----
    ull wt0[23], wt1[23];
    ull bias0, bias1, wD0, wD1;
    {
        const ull* blk = reinterpret_cast<const ull*>(gW3) + (u * 2 + par) * 50;
#pragma unroll
        for (int k = 0; k < 23; ++k) { wt0[k] = blk[k]; wt1[k] = blk[25 + k]; }
        bias0 = blk[23]; wD0 = blk[24];
        bias1 = blk[48]; wD1 = blk[49];
    }
    // Wd half for parity-split dot (5 ulonglong2 = pairs for k in [par*10, par*10+10))
    ulonglong2 wdq[5];
    {
        const ulonglong2* wsrc = reinterpret_cast<const ulonglong2*>(gWdD4) + par * 5;
#pragma unroll
        for (int j = 0; j < 5; ++j) wdq[j] = wsrc[j];
    }
    const ull cinit = (par == 0) ? *reinterpret_cast<const ull*>(&gC1) : 0ull;
    const float m0  = par ? 1.0f : 0.5f;     // gate0 affine (g vs i)
    const float c0a = par ? 0.0f : 0.5f;

    const int vbase = blockIdx.x * VPC + grp * (2 * PPT);

    // ---- per-pair state ----
    ull cc[PPT], qq[PPT], base0[PPT], base1[PPT];
#pragma unroll
    for (int p = 0; p < PPT; ++p) {
        const int vA = vbase + 2 * p, vB = vA + 1;
        cc[p] = pack2(c0[vA * H + u], c0[vB * H + u]);
        if (par == 0)
            hbuf[0][(grp * PPT + p) * RSTRIDE + u] =
                pack2(h0[vA * H + u], h0[vB * H + u]);
        float pA = init_state[2 * vA], sA = init_state[2 * vA + 1];
        float pB = init_state[2 * vB], sB = init_state[2 * vB + 1];
        qq[p] = pack2(pA, pB);
        ull Dp = pack2(sA - pA, sB - pB);
        base0[p] = bias0; ffma2(base0[p], wD0, Dp);   // fold D-row + bias
        base1[p] = bias1; ffma2(base1[p], wD1, Dp);
    }
    __syncthreads();

    const float2* lead2 = reinterpret_cast<const float2*>(lead_inputs);
    const bool extras = (out_size >= NT * NVEH + NVEH + 2 * NVEH * H);

#pragma unroll 1
    for (int t = 0; t < NT; ++t) {
        __syncthreads();                       // h(t) visible
        const ull* rb  = hbuf[t & 1];
        ull*       wbv = hbuf[(t + 1) & 1];

#pragma unroll 1
        for (int p = 0; p < PPT; ++p) {
            const int gp = grp * PPT + p;
            const ull* row = rb + gp * RSTRIDE;
            const int vA = vbase + 2 * p, vB = vA + 1;

            // lead inputs for this pair (issued early; covered by dot/GEMM)
            float2 LA = lead2[(size_t)vA * NT + t];
            float2 LB = lead2[(size_t)vB * NT + t];

            // ---- parity-split Wd dot on h(t): q(t) = q(t-1) + 0.7*dot + c1 ----
            if (t > 0) {
                const ulonglong2* dh =
                    reinterpret_cast<const ulonglong2*>(row + par * 10);
                ull pa = cinit, pb = 0ull;
#pragma unroll
                for (int j = 0; j < 5; ++j) {
                    ulonglong2 hv = dh[j];
                    ffma2(pa, wdq[j].x, hv.x);
                    ffma2(pb, wdq[j].y, hv.y);
                }
                ull part = add2(pa, pb);
                ull peer = __shfl_xor_sync(0xffffffffu, part, 1);
                qq[p] = add2(qq[p], add2(part, peer));
                if (r == 0) {
                    out[(size_t)(t - 1) * NVEH + vA] = lo32(qq[p]);
                    out[(size_t)(t - 1) * NVEH + vB] = hi32(qq[p]);
                }
            }

            // ---- GEMM: 23 rows x 2 gates, pair-packed ----
            ull lpz = pack2(LA.x, LB.x);
            ull lsz = pack2(LA.y, LB.y);
            ull a0 = base0[p], a1 = base1[p];
            ffma2(a0, wt0[0], qq[p]); ffma2(a1, wt1[0], qq[p]);
            ffma2(a0, wt0[1], lpz);   ffma2(a1, wt1[1], lpz);
            ffma2(a0, wt0[2], lsz);   ffma2(a1, wt1[2], lsz);

            const ulonglong2* rp = reinterpret_cast<const ulonglong2*>(row);
            {
                ulonglong2 hq[5];
#pragma unroll
                for (int j = 0; j < 5; ++j) hq[j] = rp[j];
#pragma unroll
                for (int j = 0; j < 5; ++j) {
                    ffma2(a0, wt0[3 + 2 * j],     hq[j].x);
                    ffma2(a1, wt1[3 + 2 * j],     hq[j].x);
                    ffma2(a0, wt0[3 + 2 * j + 1], hq[j].y);
                    ffma2(a1, wt1[3 + 2 * j + 1], hq[j].y);
                }
#pragma unroll
                for (int j = 0; j < 5; ++j) hq[j] = rp[5 + j];
#pragma unroll
                for (int j = 0; j < 5; ++j) {
                    ffma2(a0, wt0[13 + 2 * j],     hq[j].x);
                    ffma2(a1, wt1[13 + 2 * j],     hq[j].x);
                    ffma2(a0, wt0[13 + 2 * j + 1], hq[j].y);
                    ffma2(a1, wt1[13 + 2 * j + 1], hq[j].y);
                }
            }

            // ---- gates (uniform code, both parities) ----
            float t00 = fast_tanh(lo32(a0)), t01 = fast_tanh(hi32(a0));
            float t10 = fast_tanh(lo32(a1)), t11 = fast_tanh(hi32(a1));
            ull g0 = pack2(fmaf(m0, t00, c0a), fmaf(m0, t01, c0a));
            ull g1 = pack2(fmaf(0.5f, t10, 0.5f), fmaf(0.5f, t11, 0.5f));
            ull pg0 = __shfl_xor_sync(0xffffffffu, g0, 1);
            ull pg1 = __shfl_xor_sync(0xffffffffu, g1, 1);
            ull si = par ? pg0 : g0;
            ull tg = par ? g0  : pg0;
            ull sf = par ? pg1 : g1;
            ull so = par ? g1  : pg1;
            ull cn = mul2(si, tg);
            ffma2(cn, sf, cc[p]);
            cc[p] = cn;
            ull thc = pack2(fast_tanh(lo32(cn)), fast_tanh(hi32(cn)));
            if (par == 0)
                wbv[gp * RSTRIDE + u] = mul2(so, thc);   // h(t+1) pair
        }
    }

    // ---- epilogue: final dot on h(NT), last output + extras ----
    __syncthreads();
    const ull* fb = hbuf[NT & 1];    // NT even -> hbuf[0]
    float* hout  = out + (size_t)NT * NVEH + NVEH;
    float* cout2 = hout + (size_t)NVEH * H;

#pragma unroll 1
    for (int p = 0; p < PPT; ++p) {
        const int gp = grp * PPT + p;
        const ull* row = fb + gp * RSTRIDE;
        const int vA = vbase + 2 * p, vB = vA + 1;

        const ulonglong2* dh = reinterpret_cast<const ulonglong2*>(row + par * 10);
        ull pa = cinit, pb = 0ull;
#pragma unroll
        for (int j = 0; j < 5; ++j) {
            ulonglong2 hv = dh[j];
            ffma2(pa, wdq[j].x, hv.x);
            ffma2(pb, wdq[j].y, hv.y);
        }
        ull part = add2(pa, pb);
        ull peer = __shfl_xor_sync(0xffffffffu, part, 1);
        qq[p] = add2(qq[p], add2(part, peer));
        if (r == 0) {
            out[(size_t)(NT - 1) * NVEH + vA] = lo32(qq[p]);
            out[(size_t)(NT - 1) * NVEH + vB] = hi32(qq[p]);
        }

        if (extras) {
            if (r == 0) {
                float DA = init_state[2 * vA + 1] - init_state[2 * vA];
                float DB = init_state[2 * vB + 1] - init_state[2 * vB];
                out[(size_t)NT * NVEH + vA] = lo32(qq[p]) + DA;
                out[(size_t)NT * NVEH + vB] = hi32(qq[p]) + DB;
            }
            if (par == 0) {
                ull hv = row[u];
                hout[vA * H + u] = lo32(hv);
                hout[vB * H + u] = hi32(hv);
                cout2[vA * H + u] = lo32(cc[p]);
                cout2[vB * H + u] = hi32(cc[p]);
            }
        }
    }
}

extern "C" void kernel_launch(void* const* d_in, const int* in_sizes, int n_in,
                              void* d_out, int out_size) {
    const float* lead_inputs = (const float*)d_in[0];
    const float* init_state  = (const float*)d_in[1];
    const float* h0          = (const float*)d_in[2];
    const float* c0          = (const float*)d_in[3];
    const float* W           = (const float*)d_in[4];
    const float* U           = (const float*)d_in[5];
    const float* b           = (const float*)d_in[6];
    const float* Wd          = (const float*)d_in[7];
    const float* bd          = (const float*)d_in[8];

    repack_kernel<<<2, 1024>>>(W, U, b, Wd, bd);
    rnncf_kernel<<<NCTA, TPC>>>(lead_inputs, init_state, h0, c0,
                                (float*)d_out, out_size);
}